// round 9
// baseline (speedup 1.0000x reference)
#include <cuda_runtime.h>

// RvNN fused kernel v7: tf32 mma with whole-layer weight residency.
// BB=8 -> CHPA 66KB, single 128KB smem weight buffer = full Wc2/Wp2/half-Wl1.
// Long barrier-free mma runs; ~15 barriers/stage vs ~40.

#define DEVINL __device__ __forceinline__
typedef unsigned int u32;
typedef unsigned long long u64;

constexpr int NTH = 512;
constexpr int BB  = 8;

// prepacked B-fragment segments (float2 units): layer2 [ks][nt<32][lane], layer3 [ks][nt<16][lane]
constexpr int OC2 = 0;       // Wc2: 16 ks x 32 nt x 32 = 16384 pairs
constexpr int OP2 = 16384;   // Wp2: 16384 pairs
constexpr int OL1 = 32768;   // Wl1: 64 ks x 16 nt x 32 = 32768 pairs
constexpr int NPAIR = 65536; // 512 KB
__device__ __align__(16) float2 g_packed[NPAIR];

// ---- smem layout (float offsets) ----
constexpr int STRU = 132;    // U/H row stride
constexpr int STRC = 516;    // CHPA row stride
constexpr int SM_U    = 0;                 // 32*132 = 4224
constexpr int SM_CHPA = 4224;              // 32*516 = 16512 (X staging aliases head)
constexpr int SM_WT   = 20736;             // 32768 floats = 16384 pairs (128 KB)
constexpr int SM_WS   = 53504;             // 4096 (Wc1/Wp1/Wl2)
constexpr int SM_Y    = 57600;             // 384
constexpr int SM_TOT  = 57984;             // 231936 bytes
// S12 aliases WT+8192 (WT dead at layer4/staging time); PART aliases WT+0.

DEVINL float sanf(float x) {
    if (isnan(x)) return 0.0f;
    if (isinf(x)) return 9999.0f;
    return x;
}

DEVINL float fast_tanh(float x) {
    float ax = fabsf(x) * 2.8853900817779268f;  // 2*log2(e)
    float e; asm("ex2.approx.f32 %0, %1;" : "=f"(e) : "f"(ax));
    float r; asm("rcp.approx.f32 %0, %1;" : "=f"(r) : "f"(e + 1.0f));
    float t = fmaf(-2.0f, r, 1.0f);
    return copysignf(t, x);
}

DEVINL float tf32f(float x) {
    u32 y; asm("cvt.rna.tf32.f32 %0, %1;" : "=r"(y) : "f"(x));
    return __uint_as_float(y);
}

DEVINL void mma8(float* d, const u32* a, u32 b0, u32 b1) {
    asm("mma.sync.aligned.m16n8k8.row.col.f32.tf32.tf32.f32 "
        "{%0,%1,%2,%3}, {%4,%5,%6,%7}, {%8,%9}, {%0,%1,%2,%3};"
        : "+f"(d[0]), "+f"(d[1]), "+f"(d[2]), "+f"(d[3])
        : "r"(a[0]), "r"(a[1]), "r"(a[2]), "r"(a[3]), "r"(b0), "r"(b1));
}

DEVINL void cpa16(void* dst, const void* src) {
    unsigned sa = (unsigned)__cvta_generic_to_shared(dst);
    asm volatile("cp.async.cg.shared.global [%0], [%1], 16;" :: "r"(sa), "l"(src));
}
DEVINL void cpa_commit() { asm volatile("cp.async.commit_group;"); }
DEVINL void cpa_wait0()  { asm volatile("cp.async.wait_group 0;"); }
DEVINL void cpa_wait1()  { asm volatile("cp.async.wait_group 1;"); }

DEVINL void load_ws(float* WS, const float* src, int nfloats, int tid) {
    for (int s = tid; s < nfloats / 4; s += NTH) cpa16(WS + s * 4, src + s * 4);
}
DEVINL void load_wt(float* WT, const float2* src, int npairs, int tid) {
    for (int s = tid; s < npairs / 2; s += NTH) cpa16((float2*)WT + s * 2, src + s * 2);
}

// ---------- prepack (same fragment layout as v6) ----------
__global__ void prepack_kernel(const float* __restrict__ Wc2,
                               const float* __restrict__ Wp2,
                               const float* __restrict__ Wl1)
{
    int idx = blockIdx.x * blockDim.x + threadIdx.x;
    if (idx >= NPAIR) return;
    const float* W; int p, N, ks, nt, lane;
    if (idx < OP2)      { W = Wc2; p = idx;       N = 256; ks = p >> 10; int rem = p & 1023; nt = rem >> 5; lane = rem & 31; }
    else if (idx < OL1) { W = Wp2; p = idx - OP2; N = 256; ks = p >> 10; int rem = p & 1023; nt = rem >> 5; lane = rem & 31; }
    else                { W = Wl1; p = idx - OL1; N = 128; ks = p >> 9;  int rem = p & 511;  nt = rem >> 5; lane = rem & 31; }
    int k0 = 8 * ks + (lane & 3);
    int n  = 8 * nt + (lane >> 2);
    float2 v;
    v.x = tf32f(W[k0 * N + n]);
    v.y = tf32f(W[(k0 + 4) * N + n]);
    g_packed[idx] = v;
}

// ---------- layer1: A[M][KA] @ W[KA][128] + b -> prelu -> U (stride STRU, tf32) ----------
template<int M, int KA>
DEVINL void layer1(const float* __restrict__ A, const float* __restrict__ WT,
                   const float* __restrict__ bg, float alpha,
                   float* __restrict__ U, int tx, int ty)
{
    constexpr int RPT = M / 16;
    float acc[RPT][4];
#pragma unroll
    for (int r = 0; r < RPT; r++)
#pragma unroll
        for (int j = 0; j < 4; j++) acc[r][j] = 0.0f;

#pragma unroll
    for (int k = 0; k < KA; k += 4) {
        float a[RPT][4];
#pragma unroll
        for (int r = 0; r < RPT; r++) {
            float4 v = *(const float4*)&A[(ty * RPT + r) * KA + k];
            a[r][0] = v.x; a[r][1] = v.y; a[r][2] = v.z; a[r][3] = v.w;
        }
#pragma unroll
        for (int j4 = 0; j4 < 4; j4++) {
            float w[4];
#pragma unroll
            for (int j = 0; j < 4; j++) w[j] = WT[(k + j4) * 128 + tx + 32 * j];
#pragma unroll
            for (int r = 0; r < RPT; r++)
#pragma unroll
                for (int j = 0; j < 4; j++)
                    acc[r][j] = fmaf(a[r][j4], w[j], acc[r][j]);
        }
    }
#pragma unroll
    for (int r = 0; r < RPT; r++)
#pragma unroll
        for (int j = 0; j < 4; j++) {
            int c = tx + 32 * j;
            float v = acc[r][j] + bg[c];
            v = (v >= 0.0f) ? v : alpha * v;
            U[(ty * RPT + r) * STRU + c] = tf32f(v);
        }
}

// ---------- layer2 (mma): whole Wc2/Wp2 resident in WT; 16 ksteps barrier-free ----------
// 16 warps, warp w covers n8-tiles {2w, 2w+1}; MT = M/16 m-tiles.
template<int M>
DEVINL void layer2(const float* __restrict__ U, const u64* __restrict__ WTp,
                   const float* __restrict__ bg, float* __restrict__ CH, int colOff,
                   int tid)
{
    constexpr int MT = M / 16;
    const int w = tid >> 5, lane = tid & 31;
    const int r = lane >> 2, cth = lane & 3;
    const u32* Uu = (const u32*)U;
    float acc[MT][2][4];
#pragma unroll
    for (int mt = 0; mt < MT; mt++)
#pragma unroll
        for (int nt = 0; nt < 2; nt++)
#pragma unroll
            for (int j = 0; j < 4; j++) acc[mt][nt][j] = 0.0f;

#pragma unroll 4
    for (int kk = 0; kk < 16; kk++) {
        const int kA = kk * 8 + cth;
        u32 a[MT][4];
#pragma unroll
        for (int mt = 0; mt < MT; mt++) {
            int base = (mt * 16 + r) * STRU + kA;
            a[mt][0] = Uu[base];
            a[mt][1] = Uu[base + 8 * STRU];
            a[mt][2] = Uu[base + 4];
            a[mt][3] = Uu[base + 8 * STRU + 4];
        }
#pragma unroll
        for (int nt = 0; nt < 2; nt++) {
            u64 b = WTp[kk * 1024 + (2 * w + nt) * 32 + lane];
            u32 b0 = (u32)b, b1 = (u32)(b >> 32);
#pragma unroll
            for (int mt = 0; mt < MT; mt++) mma8(acc[mt][nt], a[mt], b0, b1);
        }
    }
#pragma unroll
    for (int mt = 0; mt < MT; mt++)
#pragma unroll
        for (int nt = 0; nt < 2; nt++) {
            int row0 = mt * 16 + r;
            int c0 = (2 * w + nt) * 8 + 2 * cth;
            float b0v = bg[c0], b1v = bg[c0 + 1];
            float2 v0, v1;
            v0.x = tf32f(fast_tanh(acc[mt][nt][0] + b0v));
            v0.y = tf32f(fast_tanh(acc[mt][nt][1] + b1v));
            v1.x = tf32f(fast_tanh(acc[mt][nt][2] + b0v));
            v1.y = tf32f(fast_tanh(acc[mt][nt][3] + b1v));
            *(float2*)&CH[row0 * STRC + colOff + c0] = v0;
            *(float2*)&CH[(row0 + 8) * STRC + colOff + c0] = v1;
        }
}

// ---------- layer3 pass: half of K (256), split-K2 within pass ----------
// warps 0-7 = group0 (ks_local 0..15), warps 8-15 = group1 (ks_local 16..31).
// warp covers n8-tiles {2*(w&7), 2*(w&7)+1}, MT m-tiles. Accumulate across passes.
template<int M, int MT>
DEVINL void layer3_pass(const float* __restrict__ CP, const u64* __restrict__ WTp,
                        float (&acc)[MT][2][4], int pass, int tid)
{
    const int w = tid >> 5, lane = tid & 31;
    const int kg = w >> 3, wl = w & 7;
    const int r = lane >> 2, cth = lane & 3;
    const u32* Cu = (const u32*)CP;
#pragma unroll 4
    for (int kk = 0; kk < 16; kk++) {
        const int ksl = kg * 16 + kk;
        const int kA = (pass * 32 + ksl) * 8 + cth;
        u32 a[MT][4];
#pragma unroll
        for (int mt = 0; mt < MT; mt++) {
            int base = (mt * 16 + r) * STRC + kA;
            a[mt][0] = Cu[base];
            a[mt][1] = Cu[base + 8 * STRC];
            a[mt][2] = Cu[base + 4];
            a[mt][3] = Cu[base + 8 * STRC + 4];
        }
#pragma unroll
        for (int nt = 0; nt < 2; nt++) {
            u64 b = WTp[ksl * 512 + (2 * wl + nt) * 32 + lane];
            u32 b0 = (u32)b, b1 = (u32)(b >> 32);
#pragma unroll
            for (int mt = 0; mt < MT; mt++) mma8(acc[mt][nt], a[mt], b0, b1);
        }
    }
}

// group1 dumps partials to PART (aliases WT, dead), group0 reduces + tanh -> H.
template<int M, int MT>
DEVINL void layer3_reduce(float (&acc)[MT][2][4], const float* __restrict__ bl1,
                          float* __restrict__ H, float* __restrict__ PART, int tid)
{
    const int w = tid >> 5, lane = tid & 31;
    const int kg = w >> 3, wl = w & 7;
    const int r = lane >> 2, cth = lane & 3;
    if (kg == 1) {
#pragma unroll
        for (int mt = 0; mt < MT; mt++)
#pragma unroll
            for (int nt = 0; nt < 2; nt++) {
                int row0 = mt * 16 + r;
                int c0 = (2 * wl + nt) * 8 + 2 * cth;
                float2 v0 = { acc[mt][nt][0], acc[mt][nt][1] };
                float2 v1 = { acc[mt][nt][2], acc[mt][nt][3] };
                *(float2*)&PART[row0 * 128 + c0] = v0;
                *(float2*)&PART[(row0 + 8) * 128 + c0] = v1;
            }
    }
    __syncthreads();
    if (kg == 0) {
#pragma unroll
        for (int mt = 0; mt < MT; mt++)
#pragma unroll
            for (int nt = 0; nt < 2; nt++) {
                int row0 = mt * 16 + r;
                int c0 = (2 * wl + nt) * 8 + 2 * cth;
                float2 p0 = *(const float2*)&PART[row0 * 128 + c0];
                float2 p1 = *(const float2*)&PART[(row0 + 8) * 128 + c0];
                float b0 = bl1[c0], b1 = bl1[c0 + 1];
                H[row0 * STRU + c0]           = fast_tanh(acc[mt][nt][0] + p0.x + b0);
                H[row0 * STRU + c0 + 1]       = fast_tanh(acc[mt][nt][1] + p0.y + b1);
                H[(row0 + 8) * STRU + c0]     = fast_tanh(acc[mt][nt][2] + p1.x + b0);
                H[(row0 + 8) * STRU + c0 + 1] = fast_tanh(acc[mt][nt][3] + p1.y + b1);
            }
    }
}

// ---------- layer4: H[M][128] @ Wl2[128][32] + b -> prelu -> S12 / out ----------
template<int M, bool FINAL>
DEVINL void layer4(const float* __restrict__ H, const float* __restrict__ WT,
                   const float* __restrict__ bl2, float al,
                   float* __restrict__ S12, float* __restrict__ out,
                   int b0, int nb, int tx, int ty)
{
    constexpr int RPT = M / 16;
    float acc[RPT];
#pragma unroll
    for (int r = 0; r < RPT; r++) acc[r] = 0.0f;
#pragma unroll
    for (int k = 0; k < 128; k += 4) {
        float a[RPT][4];
#pragma unroll
        for (int r = 0; r < RPT; r++) {
            float4 v = *(const float4*)&H[(ty * RPT + r) * STRU + k];
            a[r][0] = v.x; a[r][1] = v.y; a[r][2] = v.z; a[r][3] = v.w;
        }
#pragma unroll
        for (int j = 0; j < 4; j++) {
            float wv = WT[(k + j) * 32 + tx];
#pragma unroll
            for (int r = 0; r < RPT; r++) acc[r] = fmaf(a[r][j], wv, acc[r]);
        }
    }
#pragma unroll
    for (int r = 0; r < RPT; r++) {
        float v = acc[r] + bl2[tx];
        v = (v >= 0.0f) ? v : al * v;
        int row = ty * RPT + r;
        if (FINAL) {
            int be = b0 + (row >> 1);
            if (be < nb) out[(size_t)be * 64 + (row & 1) * 32 + tx] = v;
        } else {
            if (tx < 12) S12[row * 12 + tx] = v;
        }
    }
}

// ---------- full combine() pipeline for M rows ----------
template<int M, bool FINAL>
DEVINL void pipeline(float* sm, int tid,
                     const float* Wc1, const float* bc1, float ac,
                     const float* bc2,
                     const float* Wp1, const float* bp1, float ap,
                     const float* bp2,
                     const float* bl1,
                     const float* Wl2, const float* bl2, float al,
                     float* out, int b0, int nb)
{
    constexpr int MT = M / 16;
    float* U    = sm + SM_U;          // also H (alias)
    float* CHPA = sm + SM_CHPA;
    float* WT   = sm + SM_WT;
    const u64* WTp = (const u64*)WT;
    float* WS   = sm + SM_WS;
    float* X    = sm + SM_CHPA;       // staged by caller
    float* Y    = sm + SM_Y;
    float* S12  = sm + SM_WT + 8192;  // WT dead at layer4 time
    float* PART = WT;                 // WT dead at reduce time
    const int tx = tid & 31, ty = tid >> 5;
    const float2* gP = g_packed;

    // A1 (Wc1 in WS) while Wc2 streams into WT
    load_ws(WS, Wc1, 24 * 128, tid); cpa_commit();
    load_wt(WT, gP + OC2, 16384, tid); cpa_commit();
    cpa_wait1();
    __syncthreads();
    layer1<M, 24>(X, WS, bc1, ac, U, tx, ty);
    cpa_wait0();
    __syncthreads();
    // B1: 16 barrier-free ksteps
    layer2<M>(U, WTp, bc2, CHPA, 0, tid);
    __syncthreads();
    // A2 (Wp1) while Wp2 streams
    load_ws(WS, Wp1, 12 * 128, tid); cpa_commit();
    load_wt(WT, gP + OP2, 16384, tid); cpa_commit();
    cpa_wait1();
    __syncthreads();
    layer1<M, 12>(Y, WS, bp1, ap, U, tx, ty);
    cpa_wait0();
    __syncthreads();
    // B2
    layer2<M>(U, WTp, bp2, CHPA, 256, tid);
    __syncthreads();
    // layer3: two K-halves of Wl1 through WT; Wl2 prefetched into WS
    float acc[MT][2][4];
#pragma unroll
    for (int mt = 0; mt < MT; mt++)
#pragma unroll
        for (int nt = 0; nt < 2; nt++)
#pragma unroll
            for (int j = 0; j < 4; j++) acc[mt][nt][j] = 0.0f;

    load_wt(WT, gP + OL1, 16384, tid); cpa_commit();           // half0
    load_ws(WS, Wl2, 128 * 32, tid); cpa_commit();             // Wl2
    cpa_wait1();                                                // half0 ready
    __syncthreads();
    layer3_pass<M, MT>(CHPA, WTp, acc, 0, tid);
    __syncthreads();
    load_wt(WT, gP + OL1 + 16384, 16384, tid); cpa_commit();   // half1
    cpa_wait0();
    __syncthreads();
    layer3_pass<M, MT>(CHPA, WTp, acc, 1, tid);
    __syncthreads();
    layer3_reduce<M, MT>(acc, bl1, U, PART, tid);  // H -> U region
    __syncthreads();
    layer4<M, FINAL>(U, WS, bl2, al, S12, out, b0, nb, tx, ty);
}

__global__ void __launch_bounds__(NTH, 1)
rvnn_kernel(const float* __restrict__ level1, const float* __restrict__ level2,
            const float* __restrict__ level3,
            const float* __restrict__ Wc1, const float* __restrict__ bc1, const float* __restrict__ ac,
            const float* __restrict__ bc2,
            const float* __restrict__ Wp1, const float* __restrict__ bp1, const float* __restrict__ ap,
            const float* __restrict__ bp2,
            const float* __restrict__ bl1,
            const float* __restrict__ Wl2, const float* __restrict__ bl2, const float* __restrict__ al,
            float* __restrict__ out, int nb)
{
    extern __shared__ float sm[];
    const int tid = threadIdx.x;
    const int b0 = blockIdx.x * BB;
    const float acv = *ac, apv = *ap, alv = *al;

    float* X   = sm + SM_CHPA;
    float* Y   = sm + SM_Y;
    float* S12 = sm + SM_WT + 8192;

    // ---- stage 1 input staging (rows = BB*4 = 32) ----
    {
        const float* src = level3 + (size_t)b0 * 96;
        int lim = (nb - b0 < BB ? nb - b0 : BB) * 96;
        for (int i = tid; i < BB * 96; i += NTH) {
            float v = (i < lim) ? sanf(src[i]) : 0.0f;
            int be = i / 96, rem = i % 96, c = rem / 12, k = rem % 12;
            int p = c >> 1, s = c & 1;
            X[(be * 4 + p) * 24 + (1 - s) * 12 + k] = v;
        }
    }
    {
        const float* src = level2 + (size_t)b0 * 48;
        int lim = (nb - b0 < BB ? nb - b0 : BB) * 48;
        for (int i = tid; i < BB * 48; i += NTH) {
            float v = (i < lim) ? sanf(src[i]) : 0.0f;
            int be = i / 48, rem = i % 48, p = rem / 12, k = rem % 12;
            Y[(be * 4 + p) * 12 + k] = v;
        }
    }
    __syncthreads();

    pipeline<32, false>(sm, tid, Wc1, bc1, acv, bc2, Wp1, bp1, apv,
                        bp2, bl1, Wl2, bl2, alv, out, b0, nb);
    __syncthreads();

    // ---- stage 2 input staging (rows = BB*2 = 16) ----
    for (int i = tid; i < 16 * 24; i += NTH) {
        int r2 = i / 24, k24 = i % 24, be = r2 >> 1, p = r2 & 1;
        int j = 2 * p + (k24 < 12 ? 1 : 0);
        int k = (k24 < 12) ? k24 : (k24 - 12);
        X[r2 * 24 + k24] = sanf(S12[(be * 4 + j) * 12 + k]);
    }
    {
        const float* src = level1 + (size_t)b0 * 24;
        int lim = (nb - b0 < BB ? nb - b0 : BB) * 24;
        for (int i = tid; i < BB * 24; i += NTH) {
            float v = (i < lim) ? sanf(src[i]) : 0.0f;
            int be = i / 24, rem = i % 24, p = rem / 12, k = rem % 12;
            Y[(be * 2 + p) * 12 + k] = v;
        }
    }
    __syncthreads();

    pipeline<16, true>(sm, tid, Wc1, bc1, acv, bc2, Wp1, bp1, apv,
                       bp2, bl1, Wl2, bl2, alv, out, b0, nb);
}

extern "C" void kernel_launch(void* const* d_in, const int* in_sizes, int n_in,
                              void* d_out, int out_size) {
    const float* level1 = (const float*)d_in[0];
    const float* level2 = (const float*)d_in[1];
    const float* level3 = (const float*)d_in[2];
    const float* Wc1 = (const float*)d_in[3];
    const float* bc1 = (const float*)d_in[4];
    const float* ac  = (const float*)d_in[5];
    const float* Wc2 = (const float*)d_in[6];
    const float* bc2 = (const float*)d_in[7];
    const float* Wp1 = (const float*)d_in[8];
    const float* bp1 = (const float*)d_in[9];
    const float* ap  = (const float*)d_in[10];
    const float* Wp2 = (const float*)d_in[11];
    const float* bp2 = (const float*)d_in[12];
    const float* Wl1 = (const float*)d_in[13];
    const float* bl1 = (const float*)d_in[14];
    const float* Wl2 = (const float*)d_in[15];
    const float* bl2 = (const float*)d_in[16];
    const float* al  = (const float*)d_in[17];
    float* out = (float*)d_out;

    int nb = in_sizes[0] / 24;
    int grid = (nb + BB - 1) / BB;
    size_t smem = (size_t)SM_TOT * sizeof(float);  // 231936 B

    prepack_kernel<<<(NPAIR + 255) / 256, 256>>>(Wc2, Wp2, Wl1);

    cudaFuncSetAttribute(rvnn_kernel, cudaFuncAttributeMaxDynamicSharedMemorySize, (int)smem);
    rvnn_kernel<<<grid, NTH, smem>>>(level1, level2, level3, Wc1, bc1, ac, bc2,
                                     Wp1, bp1, ap, bp2, bl1, Wl2, bl2, al,
                                     out, nb);
}